// round 16
// baseline (speedup 1.0000x reference)
#include <cuda_runtime.h>
#include <cuda_fp16.h>
#include <cstdint>
#include <math.h>

// Shapes: B=8, C=128, 2C=256, H=W=128, N=H*W=16384
#define B_ 8
#define C_ 128
#define C2_ 256
#define HW_ 128
#define N_ 16384
#define EPS_ 1e-5f
#define SIM_SPLITS 32

// ===================== fp16 split helpers ==================================
__device__ __forceinline__ void split_h(float v, __half& h, __half& l) {
    h = __float2half_rn(v);
    l = __float2half_rn(v - __half2float(h));
}
__device__ __forceinline__ uint32_t pack2(__half a, __half b) {
    return (uint32_t)__half_as_ushort(a) | ((uint32_t)__half_as_ushort(b) << 16);
}
__device__ __forceinline__ void mma16816(float4& d, uint32_t a0, uint32_t a1,
                                         uint32_t a2, uint32_t a3,
                                         uint32_t b0, uint32_t b1) {
    asm volatile(
        "mma.sync.aligned.m16n8k16.row.col.f32.f16.f16.f32 "
        "{%0,%1,%2,%3}, {%4,%5,%6,%7}, {%8,%9}, {%0,%1,%2,%3};"
        : "+f"(d.x), "+f"(d.y), "+f"(d.z), "+f"(d.w)
        : "r"(a0), "r"(a1), "r"(a2), "r"(a3), "r"(b0), "r"(b1));
}
__device__ __forceinline__ uint32_t smem_u32(const void* p) {
    uint32_t a;
    asm("{ .reg .u64 t; cvta.to.shared.u64 t, %1; cvt.u32.u64 %0, t; }" : "=r"(a) : "l"(p));
    return a;
}
__device__ __forceinline__ void cp_async16(uint32_t dst, const void* src) {
    asm volatile("cp.async.ca.shared.global [%0], [%1], 16;" :: "r"(dst), "l"(src) : "memory");
}
#define CP_COMMIT() asm volatile("cp.async.commit_group;" ::: "memory")
#define CP_WAIT1()  asm volatile("cp.async.wait_group 1;" ::: "memory")

// ===================== device scratch ======================================
__device__ __align__(16) uint4 g_wf16[144 * 8 * 2 * 32];
__device__ float g_avg[B_ * C2_];
__device__ float g_se[B_ * C2_];
// y stored as split fp16, packed over n: [b][c][n/2]
__device__ __align__(16) uint32_t g_yh[(size_t)B_ * C_ * N_ / 2];
__device__ __align__(16) uint32_t g_yl[(size_t)B_ * C_ * N_ / 2];
__device__ __align__(16) float g_simp[(size_t)B_ * SIM_SPLITS * C_ * C_];
__device__ __align__(16) float g_p[B_ * C_ * C_];

// ===== 1. weight prep: conv_w [co][ci][tap] -> fp16 k16 fragments ==========
__global__ void prep_wf16_kernel(const float* __restrict__ conv_w) {
    int idx = blockIdx.x * blockDim.x + threadIdx.x;
    if (idx >= 144 * 8 * 2 * 32) return;
    int lane = idx & 31;
    int s    = (idx >> 5) & 1;
    int mt   = (idx >> 6) & 7;
    int ks2  = idx >> 9;
    int j2   = ks2 & 1;
    int cib  = (ks2 >> 1) & 7;
    int tap  = ks2 >> 4;
    int tg = lane & 3, gp = lane >> 2;
    int co  = mt * 16 + gp;
    int ci0 = cib * 32 + j2 * 16;

    float w[8];
    w[0] = conv_w[((co    ) * C2_ + ci0 + 2 * tg    ) * 9 + tap];
    w[1] = conv_w[((co    ) * C2_ + ci0 + 2 * tg + 1) * 9 + tap];
    w[2] = conv_w[((co + 8) * C2_ + ci0 + 2 * tg    ) * 9 + tap];
    w[3] = conv_w[((co + 8) * C2_ + ci0 + 2 * tg + 1) * 9 + tap];
    w[4] = conv_w[((co    ) * C2_ + ci0 + 2 * tg + 8) * 9 + tap];
    w[5] = conv_w[((co    ) * C2_ + ci0 + 2 * tg + 9) * 9 + tap];
    w[6] = conv_w[((co + 8) * C2_ + ci0 + 2 * tg + 8) * 9 + tap];
    w[7] = conv_w[((co + 8) * C2_ + ci0 + 2 * tg + 9) * 9 + tap];

    __half h[8], l[8];
    #pragma unroll
    for (int i = 0; i < 8; i++) split_h(w[i], h[i], l[i]);

    uint4 v;
    if (s == 0) {
        v.x = pack2(h[0], h[1]); v.y = pack2(h[2], h[3]);
        v.z = pack2(h[4], h[5]); v.w = pack2(h[6], h[7]);
    } else {
        v.x = pack2(l[0], l[1]); v.y = pack2(l[2], l[3]);
        v.z = pack2(l[4], l[5]); v.w = pack2(l[6], l[7]);
    }
    g_wf16[idx] = v;
}

// ===== 2. global average pool ==============================================
__global__ void avgpool_kernel(const float* __restrict__ x1,
                               const float* __restrict__ x2) {
    int bc = blockIdx.x;
    int b = bc >> 8, c = bc & 255;
    const float* src = (c < C_) ? (x1 + ((size_t)(b * C_ + c)) * N_)
                                : (x2 + ((size_t)(b * C_ + (c - C_))) * N_);
    float s = 0.f;
    const float4* s4 = (const float4*)src;
    for (int i = threadIdx.x; i < N_ / 4; i += 256) {
        float4 v = s4[i];
        s += v.x + v.y + v.z + v.w;
    }
    for (int o = 16; o; o >>= 1) s += __shfl_down_sync(0xffffffffu, s, o);
    __shared__ float ws[8];
    int lane = threadIdx.x & 31, wid = threadIdx.x >> 5;
    if (lane == 0) ws[wid] = s;
    __syncthreads();
    if (threadIdx.x == 0) {
        float t = 0.f;
        #pragma unroll
        for (int i = 0; i < 8; i++) t += ws[i];
        g_avg[bc] = t * (1.f / (float)N_);
    }
}

// ===== 3. SE MLP ===========================================================
__global__ void se_mlp_kernel(const float* __restrict__ se_w1,
                              const float* __restrict__ se_w2) {
    __shared__ float avg_s[C2_];
    __shared__ float h_s[32];
    int tid = threadIdx.x;
    for (int b = 0; b < B_; b++) {
        avg_s[tid] = g_avg[b * C2_ + tid];
        __syncthreads();
        if (tid < 32) {
            float s = 0.f;
            #pragma unroll 8
            for (int k = 0; k < C2_; k++) s += avg_s[k] * se_w1[tid * C2_ + k];
            h_s[tid] = fmaxf(s, 0.f);
        }
        __syncthreads();
        {
            float s = 0.f;
            #pragma unroll
            for (int j = 0; j < 32; j++) s += h_s[j] * se_w2[tid * 32 + j];
            g_se[b * C2_ + tid] = 1.f / (1.f + expf(-s));
        }
        __syncthreads();
    }
}

// ===== 4. conv 3x3, fp16 k16, 2-term, 4-tile ring, 2-chunk supersteps ======
#define CB_STR 136
#define CB_TILE (16 * CB_STR)
#define RAW_SLOT 20
#define RAW_BUF (256 * RAW_SLOT)

__device__ __forceinline__ void conv_build_halo(
    uint32_t* __restrict__ th,
    const float* __restrict__ x1, const float* __restrict__ x2,
    int b, int hh, int cib, int k2, int seg)
{
    const int ci0 = cib * 32 + 2 * k2;
    const float se0 = g_se[b * C2_ + ci0];
    const float se1 = g_se[b * C2_ + ci0 + 1];
    const float* s0 = ((ci0 < C_) ? (x1 + ((size_t)(b * C_ + ci0)) * N_)
                                  : (x2 + ((size_t)(b * C_ + ci0 - C_)) * N_))
                      + (size_t)hh * HW_ + seg * 8;
    const int ci1 = ci0 + 1;
    const float* s1 = ((ci1 < C_) ? (x1 + ((size_t)(b * C_ + ci1)) * N_)
                                  : (x2 + ((size_t)(b * C_ + ci1 - C_)) * N_))
                      + (size_t)hh * HW_ + seg * 8;
    float4 a0 = ((const float4*)s0)[0];
    float4 a1 = ((const float4*)s0)[1];
    float4 b0 = ((const float4*)s1)[0];
    float4 b1 = ((const float4*)s1)[1];
    const float v0[8] = {a0.x, a0.y, a0.z, a0.w, a1.x, a1.y, a1.z, a1.w};
    const float v1[8] = {b0.x, b0.y, b0.z, b0.w, b1.x, b1.y, b1.z, b1.w};
    uint32_t* dh = th + k2 * CB_STR + 1 + seg * 8;
    #pragma unroll
    for (int e = 0; e < 8; e++)
        dh[e] = pack2(__float2half_rn(v0[e] * se0), __float2half_rn(v1[e] * se1));
}

__device__ __forceinline__ void conv_stage(
    float* __restrict__ rawbuf,
    const float* __restrict__ x1, const float* __restrict__ x2,
    int b, int hh, int cib, int tid)
{
    const int k2 = tid >> 4, seg = tid & 15;
    const int ci0 = cib * 32 + 2 * k2;
    const float* s0 = ((ci0 < C_) ? (x1 + ((size_t)(b * C_ + ci0)) * N_)
                                  : (x2 + ((size_t)(b * C_ + ci0 - C_)) * N_))
                      + (size_t)hh * HW_ + seg * 8;
    const int ci1 = ci0 + 1;
    const float* s1 = ((ci1 < C_) ? (x1 + ((size_t)(b * C_ + ci1)) * N_)
                                  : (x2 + ((size_t)(b * C_ + ci1 - C_)) * N_))
                      + (size_t)hh * HW_ + seg * 8;
    const uint32_t dst = smem_u32(rawbuf + tid * RAW_SLOT);
    cp_async16(dst,      s0);
    cp_async16(dst + 16, s0 + 4);
    cp_async16(dst + 32, s1);
    cp_async16(dst + 48, s1 + 4);
}

__device__ __forceinline__ void conv_xform(
    uint32_t* __restrict__ th,
    const float* __restrict__ rawbuf, int b, int cib, int tid)
{
    const int k2 = tid >> 4, seg = tid & 15;
    const int ci0 = cib * 32 + 2 * k2;
    const float se0 = g_se[b * C2_ + ci0];
    const float se1 = g_se[b * C2_ + ci0 + 1];
    const float* s = rawbuf + tid * RAW_SLOT;
    float4 a0 = ((const float4*)s)[0];
    float4 a1 = ((const float4*)s)[1];
    float4 b0 = ((const float4*)s)[2];
    float4 b1 = ((const float4*)s)[3];
    const float v0[8] = {a0.x, a0.y, a0.z, a0.w, a1.x, a1.y, a1.z, a1.w};
    const float v1[8] = {b0.x, b0.y, b0.z, b0.w, b1.x, b1.y, b1.z, b1.w};
    uint32_t* dh = th + k2 * CB_STR + 1 + seg * 8;
    #pragma unroll
    for (int e = 0; e < 8; e++)
        dh[e] = pack2(__float2half_rn(v0[e] * se0), __float2half_rn(v1[e] * se1));
}

__global__ void __launch_bounds__(256, 2)
conv_mma_kernel(const float* __restrict__ x1, const float* __restrict__ x2,
                const float* __restrict__ bn_gamma, const float* __restrict__ bn_beta,
                const float* __restrict__ bn_mean, const float* __restrict__ bn_var) {
    extern __shared__ uint32_t cvsu[];   // packed hi tiles [4] | raw [2]
    float* raws = (float*)(cvsu + 4 * CB_TILE);

    const int tid = threadIdx.x;
    const int wid = tid >> 5, lane = tid & 31;
    const int warpM = wid >> 2, warpN = wid & 3;
    const int h = blockIdx.x, b = blockIdx.y;

    float4 acc[4][4];
    #pragma unroll
    for (int m = 0; m < 4; m++)
        #pragma unroll
        for (int n = 0; n < 4; n++) acc[m][n] = make_float4(0.f, 0.f, 0.f, 0.f);

    const int bk2 = tid >> 4;
    const int bseg = tid & 15;

    const int tg = lane & 3;
    const int gp = lane >> 2;
    const int cbase = warpN * 32 + gp;

    for (int i = tid; i < 128; i += 256) {
        const int t = i >> 5;
        const int r = (i & 31) >> 1;
        const int c = (i & 1) ? 129 : 0;
        cvsu[t * CB_TILE + r * CB_STR + c] = 0u;
    }

    int vh[3], vk[3], nvh = 0;
    #pragma unroll
    for (int dh = -1; dh <= 1; dh++) {
        const int hh = h + dh;
        if (hh >= 0 && hh < HW_) { vh[nvh] = hh; vk[nvh] = dh + 1; nvh++; }
    }
    const int nb = nvh * 8;

    if (nb > 1) { conv_stage(raws + RAW_BUF, x1, x2, b, vh[1 >> 3], 1, tid); CP_COMMIT(); }
    if (nb > 2) { conv_stage(raws,           x1, x2, b, vh[2 >> 3], 2, tid); CP_COMMIT(); }
    conv_build_halo(cvsu, x1, x2, b, vh[0], 0, bk2, bseg);
    if (nb > 1) {
        CP_WAIT1();
        conv_xform(cvsu + CB_TILE, raws + RAW_BUF, b, 1, tid);
        if (nb > 3) { conv_stage(raws + RAW_BUF, x1, x2, b, vh[3 >> 3], 3, tid); CP_COMMIT(); }
    }
    __syncthreads();

    for (int a = 0; a < nb; a += 2) {
        #pragma unroll
        for (int half = 0; half < 2; half++) {
            const int q = a + half;
            const int khi = vk[q >> 3], cib = q & 7;
            const uint32_t* th = cvsu + (q & 3) * CB_TILE;

            #pragma unroll
            for (int kwi = 0; kwi < 3; kwi++) {
                const int tap = khi * 3 + kwi;
                #pragma unroll
                for (int j2 = 0; j2 < 2; j2++) {
                    const int ks2 = (tap * 8 + cib) * 2 + j2;
                    const int k2a = j2 * 8 + tg;
                    const int col = cbase + kwi;

                    uint32_t bh0[4], bh1[4];
                    #pragma unroll
                    for (int nt = 0; nt < 4; nt++) {
                        bh0[nt] = th[(k2a    ) * CB_STR + col + nt * 8];
                        bh1[nt] = th[(k2a + 4) * CB_STR + col + nt * 8];
                    }

                    uint4 ah[4];
                    #pragma unroll
                    for (int m = 0; m < 4; m++)
                        ah[m] = g_wf16[((size_t)(ks2 * 8 + warpM * 4 + m) * 2) * 32 + lane];

                    #pragma unroll
                    for (int m = 0; m < 4; m++)
                        #pragma unroll
                        for (int nt = 0; nt < 4; nt++)
                            mma16816(acc[m][nt], ah[m].x, ah[m].y, ah[m].z, ah[m].w, bh0[nt], bh1[nt]);

                    uint4 al[4];
                    #pragma unroll
                    for (int m = 0; m < 4; m++)
                        al[m] = g_wf16[((size_t)(ks2 * 8 + warpM * 4 + m) * 2 + 1) * 32 + lane];

                    #pragma unroll
                    for (int m = 0; m < 4; m++)
                        #pragma unroll
                        for (int nt = 0; nt < 4; nt++)
                            mma16816(acc[m][nt], al[m].x, al[m].y, al[m].z, al[m].w, bh0[nt], bh1[nt]);
                }

                if (kwi == 0 && q + 2 < nb) {
                    CP_WAIT1();
                    conv_xform(cvsu + ((q + 2) & 3) * CB_TILE,
                               raws + ((q + 2) & 1) * RAW_BUF, b, (q + 2) & 7, tid);
                    if (q + 4 < nb) {
                        conv_stage(raws + ((q + 4) & 1) * RAW_BUF, x1, x2,
                                   b, vh[(q + 4) >> 3], (q + 4) & 7, tid);
                        CP_COMMIT();
                    }
                }
            }
        }
        __syncthreads();
    }

    // epilogue: BN + ReLU, then split-fp16 store (pairs over n)
    #pragma unroll
    for (int m = 0; m < 4; m++) {
        const int co0 = warpM * 64 + m * 16 + gp;
        const int co1 = co0 + 8;
        const float inv0 = bn_gamma[co0] * rsqrtf(bn_var[co0] + EPS_);
        const float bia0 = bn_beta[co0] - bn_mean[co0] * inv0;
        const float inv1 = bn_gamma[co1] * rsqrtf(bn_var[co1] + EPS_);
        const float bia1 = bn_beta[co1] - bn_mean[co1] * inv1;
        #pragma unroll
        for (int nt = 0; nt < 4; nt++) {
            const int w = warpN * 32 + nt * 8 + tg * 2;
            float yx = fmaxf(acc[m][nt].x * inv0 + bia0, 0.f);
            float yy = fmaxf(acc[m][nt].y * inv0 + bia0, 0.f);
            float zx = fmaxf(acc[m][nt].z * inv1 + bia1, 0.f);
            float zy = fmaxf(acc[m][nt].w * inv1 + bia1, 0.f);
            __half hx, lx, hy, ly, hz, lz, hw2, lw2;
            split_h(yx, hx, lx); split_h(yy, hy, ly);
            split_h(zx, hz, lz); split_h(zy, hw2, lw2);
            const size_t i0 = (((size_t)(b * C_ + co0)) * N_ + (size_t)h * HW_ + w) >> 1;
            const size_t i1 = (((size_t)(b * C_ + co1)) * N_ + (size_t)h * HW_ + w) >> 1;
            g_yh[i0] = pack2(hx, hy);  g_yl[i0] = pack2(lx, ly);
            g_yh[i1] = pack2(hz, hw2); g_yl[i1] = pack2(lz, lw2);
        }
    }
}

// ===== 5. sim = Q Q^T via fp16 mma, 2-term, split-K=32 =====================
#define SQ_STR 20
#define SQ_TILE (128 * SQ_STR)

// build: pure u32 copy from split-fp16 y (pairs over k = n)
__device__ __forceinline__ void sim_build16(uint32_t* __restrict__ qh,
                                            uint32_t* __restrict__ ql,
                                            size_t rowbase_u32, int k0g_u32,
                                            int c, int k2b) {
    const size_t idx = rowbase_u32 + (size_t)c * (N_ / 2) + k0g_u32 + k2b;
    uint4 vh0 = *(const uint4*)(g_yh + idx);
    uint4 vh1 = *(const uint4*)(g_yh + idx + 4);
    uint4 vl0 = *(const uint4*)(g_yl + idx);
    uint4 vl1 = *(const uint4*)(g_yl + idx + 4);
    *(uint4*)(qh + c * SQ_STR + k2b)     = vh0;
    *(uint4*)(qh + c * SQ_STR + k2b + 4) = vh1;
    *(uint4*)(ql + c * SQ_STR + k2b)     = vl0;
    *(uint4*)(ql + c * SQ_STR + k2b + 4) = vl1;
}

__global__ void __launch_bounds__(256, 2)
sim_mma_kernel() {
    extern __shared__ uint32_t smsu[];
    const int tid = threadIdx.x;
    const int wid = tid >> 5, lane = tid & 31;
    const int warpM = wid >> 2, warpN = wid & 3;
    const int tg = lane & 3, gp = lane >> 2;
    const int split = blockIdx.x, b = blockIdx.y;
    const size_t rowbase = (size_t)b * C_ * (N_ / 2);
    const int k0gu = split * ((N_ / SIM_SPLITS) / 2);

    const int bc = tid >> 1, bk2 = (tid & 1) * 8;

    float4 acc[4][4];
    #pragma unroll
    for (int m = 0; m < 4; m++)
        #pragma unroll
        for (int n = 0; n < 4; n++) acc[m][n] = make_float4(0.f, 0.f, 0.f, 0.f);

    sim_build16(smsu, smsu + SQ_TILE, rowbase, k0gu, bc, bk2);
    __syncthreads();

    const int NCH = (N_ / SIM_SPLITS) / 32;   // 16
    for (int ch = 0; ch < NCH; ch++) {
        const uint32_t* qh = smsu + (ch & 1) * (2 * SQ_TILE);
        const uint32_t* ql = qh + SQ_TILE;

        #pragma unroll
        for (int j2 = 0; j2 < 2; j2++) {
            const int k2a = j2 * 8 + tg;
            uint32_t ah[4][4], al[4][4];
            #pragma unroll
            for (int m = 0; m < 4; m++) {
                const int row = warpM * 64 + m * 16 + gp;
                ah[m][0] = qh[row * SQ_STR + k2a];
                ah[m][1] = qh[(row + 8) * SQ_STR + k2a];
                ah[m][2] = qh[row * SQ_STR + k2a + 4];
                ah[m][3] = qh[(row + 8) * SQ_STR + k2a + 4];
                al[m][0] = ql[row * SQ_STR + k2a];
                al[m][1] = ql[(row + 8) * SQ_STR + k2a];
                al[m][2] = ql[row * SQ_STR + k2a + 4];
                al[m][3] = ql[(row + 8) * SQ_STR + k2a + 4];
            }
            uint32_t bh0[4], bh1[4];
            #pragma unroll
            for (int nt = 0; nt < 4; nt++) {
                const int rb = warpN * 32 + nt * 8 + gp;
                bh0[nt] = qh[rb * SQ_STR + k2a];
                bh1[nt] = qh[rb * SQ_STR + k2a + 4];
            }
            #pragma unroll
            for (int m = 0; m < 4; m++)
                #pragma unroll
                for (int nt = 0; nt < 4; nt++) {
                    mma16816(acc[m][nt], ah[m][0], ah[m][1], ah[m][2], ah[m][3], bh0[nt], bh1[nt]);
                    mma16816(acc[m][nt], al[m][0], al[m][1], al[m][2], al[m][3], bh0[nt], bh1[nt]);
                }
        }
        if (ch + 1 < NCH)
            sim_build16(smsu + ((ch + 1) & 1) * (2 * SQ_TILE),
                        smsu + ((ch + 1) & 1) * (2 * SQ_TILE) + SQ_TILE,
                        rowbase, k0gu + (ch + 1) * 16, bc, bk2);
        __syncthreads();
    }

    float* dst = g_simp + (((size_t)(b * SIM_SPLITS + split)) * C_ * C_);
    #pragma unroll
    for (int m = 0; m < 4; m++) {
        const int c0 = warpM * 64 + m * 16 + gp;
        #pragma unroll
        for (int nt = 0; nt < 4; nt++) {
            const int d = warpN * 32 + nt * 8 + tg * 2;
            *(float2*)(dst + (size_t)c0 * C_ + d)       = make_float2(acc[m][nt].x, acc[m][nt].y);
            *(float2*)(dst + (size_t)(c0 + 8) * C_ + d) = make_float2(acc[m][nt].z, acc[m][nt].w);
        }
    }
}

// ===== 6. softmax(max - sim) == exp(min - sim)/sum =========================
__global__ void softmax_kernel() {
    const int c = blockIdx.x, b = blockIdx.y;
    const int d = threadIdx.x;
    float s = 0.f;
    #pragma unroll 8
    for (int sp = 0; sp < SIM_SPLITS; sp++)
        s += g_simp[(((size_t)(b * SIM_SPLITS + sp)) * C_ + c) * C_ + d];

    __shared__ float red[128];
    red[d] = s;
    __syncthreads();
    for (int st = 64; st > 0; st >>= 1) {
        if (d < st) red[d] = fminf(red[d], red[d + st]);
        __syncthreads();
    }
    const float mn = red[0];
    __syncthreads();
    const float e = expf(mn - s);
    red[d] = e;
    __syncthreads();
    for (int st = 64; st > 0; st >>= 1) {
        if (d < st) red[d] += red[d + st];
        __syncthreads();
    }
    g_p[(b * C_ + c) * C_ + d] = e / red[0];
}

// ===== 7. feat = P @ Q via pure fp16 mma (1-term); out = gamma*feat + y ====
#define FQ_STR 136
#define FQ_TILE (16 * FQ_STR)

__global__ void __launch_bounds__(256, 2)
feat_mma_kernel(const float* __restrict__ gamma, float* __restrict__ out) {
    extern __shared__ uint32_t fmsu[];
    uint32_t* Ph = fmsu;            // [c 128][d2 16] stride 20
    uint32_t* Qh = fmsu + SQ_TILE;  // [d2 16][n 128] stride 136

    const int tid = threadIdx.x;
    const int wid = tid >> 5, lane = tid & 31;
    const int warpM = wid >> 2, warpN = wid & 3;
    const int tg = lane & 3, gp = lane >> 2;
    const int n0 = blockIdx.x * 128, b = blockIdx.y;

    const size_t rowbase = (size_t)b * C_ * (N_ / 2);
    const float* psrc = g_p + (size_t)b * C_ * C_;

    float4 acc[4][4];
    #pragma unroll
    for (int m = 0; m < 4; m++)
        #pragma unroll
        for (int n = 0; n < 4; n++) acc[m][n] = make_float4(0.f, 0.f, 0.f, 0.f);

    const int pc = tid >> 1, pk2 = (tid & 1) * 8;
    const int qd2 = tid >> 4, qns = (tid & 15) * 8;

    for (int ch = 0; ch < 4; ch++) {
        const int d0 = ch * 32;
        __syncthreads();
        // P tile (hi only), pack from f32 probs
        {
            const float* src = psrc + (size_t)pc * C_ + d0 + 2 * pk2;
            #pragma unroll
            for (int e = 0; e < 8; e++) {
                float2 v = *(const float2*)(src + 2 * e);
                Ph[pc * SQ_STR + pk2 + e] =
                    pack2(__float2half_rn(v.x), __float2half_rn(v.y));
            }
        }
        // Q tile (hi only): read packed-over-n rows, transpose pairs via PRMT
        {
            const int r0 = d0 + 2 * qd2;
            const size_t i0 = rowbase + (size_t)r0 * (N_ / 2) + ((n0 + qns) >> 1);
            const size_t i1 = i0 + (N_ / 2);
            uint4 ra = *(const uint4*)(g_yh + i0);   // row d=r0,   n pairs
            uint4 rb = *(const uint4*)(g_yh + i1);   // row d=r0+1, n pairs
            const uint32_t a[4] = {ra.x, ra.y, ra.z, ra.w};
            const uint32_t bb[4] = {rb.x, rb.y, rb.z, rb.w};
            uint32_t* dst = Qh + qd2 * FQ_STR + qns;
            #pragma unroll
            for (int j = 0; j < 4; j++) {
                dst[2 * j]     = __byte_perm(a[j], bb[j], 0x5410);  // n=2j:   (d0,d1)
                dst[2 * j + 1] = __byte_perm(a[j], bb[j], 0x7632);  // n=2j+1: (d0,d1)
            }
        }
        __syncthreads();

        #pragma unroll
        for (int j2 = 0; j2 < 2; j2++) {
            const int k2a = j2 * 8 + tg;
            uint32_t ah[4][4];
            #pragma unroll
            for (int m = 0; m < 4; m++) {
                const int row = warpM * 64 + m * 16 + gp;
                ah[m][0] = Ph[row * SQ_STR + k2a];
                ah[m][1] = Ph[(row + 8) * SQ_STR + k2a];
                ah[m][2] = Ph[row * SQ_STR + k2a + 4];
                ah[m][3] = Ph[(row + 8) * SQ_STR + k2a + 4];
            }
            uint32_t bh0[4], bh1[4];
            #pragma unroll
            for (int nt = 0; nt < 4; nt++) {
                const int cb = warpN * 32 + nt * 8 + gp;
                bh0[nt] = Qh[(k2a    ) * FQ_STR + cb];
                bh1[nt] = Qh[(k2a + 4) * FQ_STR + cb];
            }
            #pragma unroll
            for (int m = 0; m < 4; m++)
                #pragma unroll
                for (int nt = 0; nt < 4; nt++)
                    mma16816(acc[m][nt], ah[m][0], ah[m][1], ah[m][2], ah[m][3],
                             bh0[nt], bh1[nt]);
        }
    }

    const float g0 = gamma[0];
    #pragma unroll
    for (int m = 0; m < 4; m++) {
        const int co0 = warpM * 64 + m * 16 + gp;
        const int co1 = co0 + 8;
        #pragma unroll
        for (int nt = 0; nt < 4; nt++) {
            const int w = warpN * 32 + nt * 8 + tg * 2;
            const size_t a0 = ((size_t)(b * C_ + co0)) * N_ + n0 + w;
            const size_t a1 = ((size_t)(b * C_ + co1)) * N_ + n0 + w;
            const uint32_t h0 = g_yh[a0 >> 1], l0 = g_yl[a0 >> 1];
            const uint32_t h1 = g_yh[a1 >> 1], l1 = g_yl[a1 >> 1];
            __half2 H0 = *(const __half2*)&h0, L0 = *(const __half2*)&l0;
            __half2 H1 = *(const __half2*)&h1, L1 = *(const __half2*)&l1;
            float2 o0, o1;
            o0.x = g0 * acc[m][nt].x + (__low2float(H0)  + __low2float(L0));
            o0.y = g0 * acc[m][nt].y + (__high2float(H0) + __high2float(L0));
            o1.x = g0 * acc[m][nt].z + (__low2float(H1)  + __low2float(L1));
            o1.y = g0 * acc[m][nt].w + (__high2float(H1) + __high2float(L1));
            *(float2*)(out + a0) = o0;
            *(float2*)(out + a1) = o1;
        }
    }
}

// ===== launch ==============================================================
extern "C" void kernel_launch(void* const* d_in, const int* in_sizes, int n_in,
                              void* d_out, int out_size) {
    const float* x1       = (const float*)d_in[0];
    const float* x2       = (const float*)d_in[1];
    const float* se_w1    = (const float*)d_in[2];
    const float* se_w2    = (const float*)d_in[3];
    const float* conv_w   = (const float*)d_in[4];
    const float* bn_gamma = (const float*)d_in[5];
    const float* bn_beta  = (const float*)d_in[6];
    const float* bn_mean  = (const float*)d_in[7];
    const float* bn_var   = (const float*)d_in[8];
    const float* gamma    = (const float*)d_in[9];
    float* out = (float*)d_out;

    const int cv_smem   = 4 * CB_TILE * 4 + 2 * RAW_BUF * 4;  // 75776
    const int sim_smem  = 4 * SQ_TILE * 4;                    // 40960
    const int feat_smem = (SQ_TILE + FQ_TILE) * 4;            // 18944
    cudaFuncSetAttribute(conv_mma_kernel, cudaFuncAttributeMaxDynamicSharedMemorySize, cv_smem);

    prep_wf16_kernel<<<(144 * 8 * 2 * 32 + 255) / 256, 256>>>(conv_w);
    avgpool_kernel<<<B_ * C2_, 256>>>(x1, x2);
    se_mlp_kernel<<<1, C2_>>>(se_w1, se_w2);
    conv_mma_kernel<<<dim3(HW_, B_), 256, cv_smem>>>(x1, x2, bn_gamma, bn_beta, bn_mean, bn_var);
    sim_mma_kernel<<<dim3(SIM_SPLITS, B_), 256, sim_smem>>>();
    softmax_kernel<<<dim3(C_, B_), 128>>>();
    feat_mma_kernel<<<dim3(N_ / 128, B_), 256, feat_smem>>>(gamma, out);
}

// round 17
// speedup vs baseline: 1.0331x; 1.0331x over previous
#include <cuda_runtime.h>
#include <cuda_fp16.h>
#include <cstdint>
#include <math.h>

// Shapes: B=8, C=128, 2C=256, H=W=128, N=H*W=16384
#define B_ 8
#define C_ 128
#define C2_ 256
#define HW_ 128
#define N_ 16384
#define EPS_ 1e-5f
#define SIM_SPLITS 32

// ===================== fp16 split helpers ==================================
__device__ __forceinline__ void split_h(float v, __half& h, __half& l) {
    h = __float2half_rn(v);
    l = __float2half_rn(v - __half2float(h));
}
__device__ __forceinline__ uint32_t pack2(__half a, __half b) {
    return (uint32_t)__half_as_ushort(a) | ((uint32_t)__half_as_ushort(b) << 16);
}
__device__ __forceinline__ void mma16816(float4& d, uint32_t a0, uint32_t a1,
                                         uint32_t a2, uint32_t a3,
                                         uint32_t b0, uint32_t b1) {
    asm volatile(
        "mma.sync.aligned.m16n8k16.row.col.f32.f16.f16.f32 "
        "{%0,%1,%2,%3}, {%4,%5,%6,%7}, {%8,%9}, {%0,%1,%2,%3};"
        : "+f"(d.x), "+f"(d.y), "+f"(d.z), "+f"(d.w)
        : "r"(a0), "r"(a1), "r"(a2), "r"(a3), "r"(b0), "r"(b1));
}
__device__ __forceinline__ uint32_t smem_u32(const void* p) {
    uint32_t a;
    asm("{ .reg .u64 t; cvta.to.shared.u64 t, %1; cvt.u32.u64 %0, t; }" : "=r"(a) : "l"(p));
    return a;
}
__device__ __forceinline__ void cp_async16(uint32_t dst, const void* src) {
    asm volatile("cp.async.ca.shared.global [%0], [%1], 16;" :: "r"(dst), "l"(src) : "memory");
}
#define CP_COMMIT() asm volatile("cp.async.commit_group;" ::: "memory")
#define CP_WAIT1()  asm volatile("cp.async.wait_group 1;" ::: "memory")

// ===================== device scratch ======================================
__device__ __align__(16) uint4 g_wf16[144 * 8 * 2 * 32];
__device__ float g_avg[B_ * C2_];
__device__ float g_se[B_ * C2_];
__device__ __align__(16) float g_y[(size_t)B_ * C_ * N_];
__device__ __align__(16) float g_simp[(size_t)B_ * SIM_SPLITS * C_ * C_];
__device__ __align__(16) float g_p[B_ * C_ * C_];

// ===== 1. weight prep: conv_w [co][ci][tap] -> fp16 k16 fragments ==========
__global__ void prep_wf16_kernel(const float* __restrict__ conv_w) {
    int idx = blockIdx.x * blockDim.x + threadIdx.x;
    if (idx >= 144 * 8 * 2 * 32) return;
    int lane = idx & 31;
    int s    = (idx >> 5) & 1;
    int mt   = (idx >> 6) & 7;
    int ks2  = idx >> 9;
    int j2   = ks2 & 1;
    int cib  = (ks2 >> 1) & 7;
    int tap  = ks2 >> 4;
    int tg = lane & 3, gp = lane >> 2;
    int co  = mt * 16 + gp;
    int ci0 = cib * 32 + j2 * 16;

    float w[8];
    w[0] = conv_w[((co    ) * C2_ + ci0 + 2 * tg    ) * 9 + tap];
    w[1] = conv_w[((co    ) * C2_ + ci0 + 2 * tg + 1) * 9 + tap];
    w[2] = conv_w[((co + 8) * C2_ + ci0 + 2 * tg    ) * 9 + tap];
    w[3] = conv_w[((co + 8) * C2_ + ci0 + 2 * tg + 1) * 9 + tap];
    w[4] = conv_w[((co    ) * C2_ + ci0 + 2 * tg + 8) * 9 + tap];
    w[5] = conv_w[((co    ) * C2_ + ci0 + 2 * tg + 9) * 9 + tap];
    w[6] = conv_w[((co + 8) * C2_ + ci0 + 2 * tg + 8) * 9 + tap];
    w[7] = conv_w[((co + 8) * C2_ + ci0 + 2 * tg + 9) * 9 + tap];

    __half h[8], l[8];
    #pragma unroll
    for (int i = 0; i < 8; i++) split_h(w[i], h[i], l[i]);

    uint4 v;
    if (s == 0) {
        v.x = pack2(h[0], h[1]); v.y = pack2(h[2], h[3]);
        v.z = pack2(h[4], h[5]); v.w = pack2(h[6], h[7]);
    } else {
        v.x = pack2(l[0], l[1]); v.y = pack2(l[2], l[3]);
        v.z = pack2(l[4], l[5]); v.w = pack2(l[6], l[7]);
    }
    g_wf16[idx] = v;
}

// ===== 2. global average pool ==============================================
__global__ void avgpool_kernel(const float* __restrict__ x1,
                               const float* __restrict__ x2) {
    int bc = blockIdx.x;
    int b = bc >> 8, c = bc & 255;
    const float* src = (c < C_) ? (x1 + ((size_t)(b * C_ + c)) * N_)
                                : (x2 + ((size_t)(b * C_ + (c - C_))) * N_);
    float s = 0.f;
    const float4* s4 = (const float4*)src;
    for (int i = threadIdx.x; i < N_ / 4; i += 256) {
        float4 v = s4[i];
        s += v.x + v.y + v.z + v.w;
    }
    for (int o = 16; o; o >>= 1) s += __shfl_down_sync(0xffffffffu, s, o);
    __shared__ float ws[8];
    int lane = threadIdx.x & 31, wid = threadIdx.x >> 5;
    if (lane == 0) ws[wid] = s;
    __syncthreads();
    if (threadIdx.x == 0) {
        float t = 0.f;
        #pragma unroll
        for (int i = 0; i < 8; i++) t += ws[i];
        g_avg[bc] = t * (1.f / (float)N_);
    }
}

// ===== 3. SE MLP ===========================================================
__global__ void se_mlp_kernel(const float* __restrict__ se_w1,
                              const float* __restrict__ se_w2) {
    __shared__ float avg_s[C2_];
    __shared__ float h_s[32];
    int tid = threadIdx.x;
    for (int b = 0; b < B_; b++) {
        avg_s[tid] = g_avg[b * C2_ + tid];
        __syncthreads();
        if (tid < 32) {
            float s = 0.f;
            #pragma unroll 8
            for (int k = 0; k < C2_; k++) s += avg_s[k] * se_w1[tid * C2_ + k];
            h_s[tid] = fmaxf(s, 0.f);
        }
        __syncthreads();
        {
            float s = 0.f;
            #pragma unroll
            for (int j = 0; j < 32; j++) s += h_s[j] * se_w2[tid * 32 + j];
            g_se[b * C2_ + tid] = 1.f / (1.f + expf(-s));
        }
        __syncthreads();
    }
}

// ===== 4. conv 3x3, fp16 k16, 2-term, 4-tile ring, 2-chunk supersteps ======
#define CB_STR 136
#define CB_TILE (16 * CB_STR)
#define RAW_SLOT 20
#define RAW_BUF (256 * RAW_SLOT)

__device__ __forceinline__ void conv_build_halo(
    uint32_t* __restrict__ th,
    const float* __restrict__ x1, const float* __restrict__ x2,
    int b, int hh, int cib, int k2, int seg)
{
    const int ci0 = cib * 32 + 2 * k2;
    const float se0 = g_se[b * C2_ + ci0];
    const float se1 = g_se[b * C2_ + ci0 + 1];
    const float* s0 = ((ci0 < C_) ? (x1 + ((size_t)(b * C_ + ci0)) * N_)
                                  : (x2 + ((size_t)(b * C_ + ci0 - C_)) * N_))
                      + (size_t)hh * HW_ + seg * 8;
    const int ci1 = ci0 + 1;
    const float* s1 = ((ci1 < C_) ? (x1 + ((size_t)(b * C_ + ci1)) * N_)
                                  : (x2 + ((size_t)(b * C_ + ci1 - C_)) * N_))
                      + (size_t)hh * HW_ + seg * 8;
    float4 a0 = ((const float4*)s0)[0];
    float4 a1 = ((const float4*)s0)[1];
    float4 b0 = ((const float4*)s1)[0];
    float4 b1 = ((const float4*)s1)[1];
    const float v0[8] = {a0.x, a0.y, a0.z, a0.w, a1.x, a1.y, a1.z, a1.w};
    const float v1[8] = {b0.x, b0.y, b0.z, b0.w, b1.x, b1.y, b1.z, b1.w};
    uint32_t* dh = th + k2 * CB_STR + 1 + seg * 8;
    #pragma unroll
    for (int e = 0; e < 8; e++)
        dh[e] = pack2(__float2half_rn(v0[e] * se0), __float2half_rn(v1[e] * se1));
}

__device__ __forceinline__ void conv_stage(
    float* __restrict__ rawbuf,
    const float* __restrict__ x1, const float* __restrict__ x2,
    int b, int hh, int cib, int tid)
{
    const int k2 = tid >> 4, seg = tid & 15;
    const int ci0 = cib * 32 + 2 * k2;
    const float* s0 = ((ci0 < C_) ? (x1 + ((size_t)(b * C_ + ci0)) * N_)
                                  : (x2 + ((size_t)(b * C_ + ci0 - C_)) * N_))
                      + (size_t)hh * HW_ + seg * 8;
    const int ci1 = ci0 + 1;
    const float* s1 = ((ci1 < C_) ? (x1 + ((size_t)(b * C_ + ci1)) * N_)
                                  : (x2 + ((size_t)(b * C_ + ci1 - C_)) * N_))
                      + (size_t)hh * HW_ + seg * 8;
    const uint32_t dst = smem_u32(rawbuf + tid * RAW_SLOT);
    cp_async16(dst,      s0);
    cp_async16(dst + 16, s0 + 4);
    cp_async16(dst + 32, s1);
    cp_async16(dst + 48, s1 + 4);
}

__device__ __forceinline__ void conv_xform(
    uint32_t* __restrict__ th,
    const float* __restrict__ rawbuf, int b, int cib, int tid)
{
    const int k2 = tid >> 4, seg = tid & 15;
    const int ci0 = cib * 32 + 2 * k2;
    const float se0 = g_se[b * C2_ + ci0];
    const float se1 = g_se[b * C2_ + ci0 + 1];
    const float* s = rawbuf + tid * RAW_SLOT;
    float4 a0 = ((const float4*)s)[0];
    float4 a1 = ((const float4*)s)[1];
    float4 b0 = ((const float4*)s)[2];
    float4 b1 = ((const float4*)s)[3];
    const float v0[8] = {a0.x, a0.y, a0.z, a0.w, a1.x, a1.y, a1.z, a1.w};
    const float v1[8] = {b0.x, b0.y, b0.z, b0.w, b1.x, b1.y, b1.z, b1.w};
    uint32_t* dh = th + k2 * CB_STR + 1 + seg * 8;
    #pragma unroll
    for (int e = 0; e < 8; e++)
        dh[e] = pack2(__float2half_rn(v0[e] * se0), __float2half_rn(v1[e] * se1));
}

__global__ void __launch_bounds__(256, 2)
conv_mma_kernel(const float* __restrict__ x1, const float* __restrict__ x2,
                const float* __restrict__ bn_gamma, const float* __restrict__ bn_beta,
                const float* __restrict__ bn_mean, const float* __restrict__ bn_var) {
    extern __shared__ uint32_t cvsu[];   // packed hi tiles [4] | raw [2]
    float* raws = (float*)(cvsu + 4 * CB_TILE);

    const int tid = threadIdx.x;
    const int wid = tid >> 5, lane = tid & 31;
    const int warpM = wid >> 2, warpN = wid & 3;
    const int h = blockIdx.x, b = blockIdx.y;

    float4 acc[4][4];
    #pragma unroll
    for (int m = 0; m < 4; m++)
        #pragma unroll
        for (int n = 0; n < 4; n++) acc[m][n] = make_float4(0.f, 0.f, 0.f, 0.f);

    const int bk2 = tid >> 4;
    const int bseg = tid & 15;

    const int tg = lane & 3;
    const int gp = lane >> 2;
    const int cbase = warpN * 32 + gp;

    for (int i = tid; i < 128; i += 256) {
        const int t = i >> 5;
        const int r = (i & 31) >> 1;
        const int c = (i & 1) ? 129 : 0;
        cvsu[t * CB_TILE + r * CB_STR + c] = 0u;
    }

    int vh[3], vk[3], nvh = 0;
    #pragma unroll
    for (int dh = -1; dh <= 1; dh++) {
        const int hh = h + dh;
        if (hh >= 0 && hh < HW_) { vh[nvh] = hh; vk[nvh] = dh + 1; nvh++; }
    }
    const int nb = nvh * 8;

    if (nb > 1) { conv_stage(raws + RAW_BUF, x1, x2, b, vh[1 >> 3], 1, tid); CP_COMMIT(); }
    if (nb > 2) { conv_stage(raws,           x1, x2, b, vh[2 >> 3], 2, tid); CP_COMMIT(); }
    conv_build_halo(cvsu, x1, x2, b, vh[0], 0, bk2, bseg);
    if (nb > 1) {
        CP_WAIT1();
        conv_xform(cvsu + CB_TILE, raws + RAW_BUF, b, 1, tid);
        if (nb > 3) { conv_stage(raws + RAW_BUF, x1, x2, b, vh[3 >> 3], 3, tid); CP_COMMIT(); }
    }
    __syncthreads();

    for (int a = 0; a < nb; a += 2) {
        #pragma unroll
        for (int half = 0; half < 2; half++) {
            const int q = a + half;
            const int khi = vk[q >> 3], cib = q & 7;
            const uint32_t* th = cvsu + (q & 3) * CB_TILE;

            #pragma unroll
            for (int kwi = 0; kwi < 3; kwi++) {
                const int tap = khi * 3 + kwi;
                #pragma unroll
                for (int j2 = 0; j2 < 2; j2++) {
                    const int ks2 = (tap * 8 + cib) * 2 + j2;
                    const int k2a = j2 * 8 + tg;
                    const int col = cbase + kwi;

                    uint32_t bh0[4], bh1[4];
                    #pragma unroll
                    for (int nt = 0; nt < 4; nt++) {
                        bh0[nt] = th[(k2a    ) * CB_STR + col + nt * 8];
                        bh1[nt] = th[(k2a + 4) * CB_STR + col + nt * 8];
                    }

                    uint4 ah[4];
                    #pragma unroll
                    for (int m = 0; m < 4; m++)
                        ah[m] = g_wf16[((size_t)(ks2 * 8 + warpM * 4 + m) * 2) * 32 + lane];

                    #pragma unroll
                    for (int m = 0; m < 4; m++)
                        #pragma unroll
                        for (int nt = 0; nt < 4; nt++)
                            mma16816(acc[m][nt], ah[m].x, ah[m].y, ah[m].z, ah[m].w, bh0[nt], bh1[nt]);

                    uint4 al[4];
                    #pragma unroll
                    for (int m = 0; m < 4; m++)
                        al[m] = g_wf16[((size_t)(ks2 * 8 + warpM * 4 + m) * 2 + 1) * 32 + lane];

                    #pragma unroll
                    for (int m = 0; m < 4; m++)
                        #pragma unroll
                        for (int nt = 0; nt < 4; nt++)
                            mma16816(acc[m][nt], al[m].x, al[m].y, al[m].z, al[m].w, bh0[nt], bh1[nt]);
                }

                if (kwi == 0 && q + 2 < nb) {
                    CP_WAIT1();
                    conv_xform(cvsu + ((q + 2) & 3) * CB_TILE,
                               raws + ((q + 2) & 1) * RAW_BUF, b, (q + 2) & 7, tid);
                    if (q + 4 < nb) {
                        conv_stage(raws + ((q + 4) & 1) * RAW_BUF, x1, x2,
                                   b, vh[(q + 4) >> 3], (q + 4) & 7, tid);
                        CP_COMMIT();
                    }
                }
            }
        }
        __syncthreads();
    }

    #pragma unroll
    for (int m = 0; m < 4; m++) {
        const int co0 = warpM * 64 + m * 16 + gp;
        const int co1 = co0 + 8;
        const float inv0 = bn_gamma[co0] * rsqrtf(bn_var[co0] + EPS_);
        const float bia0 = bn_beta[co0] - bn_mean[co0] * inv0;
        const float inv1 = bn_gamma[co1] * rsqrtf(bn_var[co1] + EPS_);
        const float bia1 = bn_beta[co1] - bn_mean[co1] * inv1;
        #pragma unroll
        for (int nt = 0; nt < 4; nt++) {
            const int w = warpN * 32 + nt * 8 + tg * 2;
            float2 v0, v1;
            v0.x = fmaxf(acc[m][nt].x * inv0 + bia0, 0.f);
            v0.y = fmaxf(acc[m][nt].y * inv0 + bia0, 0.f);
            v1.x = fmaxf(acc[m][nt].z * inv1 + bia1, 0.f);
            v1.y = fmaxf(acc[m][nt].w * inv1 + bia1, 0.f);
            *(float2*)(g_y + ((size_t)(b * C_ + co0)) * N_ + (size_t)h * HW_ + w) = v0;
            *(float2*)(g_y + ((size_t)(b * C_ + co1)) * N_ + (size_t)h * HW_ + w) = v1;
        }
    }
}

// ===== 5. sim = Q Q^T via fp16 mma, 2-term, split-K=32 =====================
#define SQ_STR 20
#define SQ_TILE (128 * SQ_STR)

__device__ __forceinline__ void sim_build16(uint32_t* __restrict__ qh,
                                            uint32_t* __restrict__ ql,
                                            const float* __restrict__ q,
                                            int kbase, int c, int k2b) {
    const float* src = q + (size_t)c * N_ + kbase + 2 * k2b;
    #pragma unroll
    for (int e = 0; e < 8; e++) {
        float2 v = *(const float2*)(src + 2 * e);
        __half h0, l0, h1, l1;
        split_h(v.x, h0, l0);
        split_h(v.y, h1, l1);
        qh[c * SQ_STR + k2b + e] = pack2(h0, h1);
        ql[c * SQ_STR + k2b + e] = pack2(l0, l1);
    }
}

__global__ void __launch_bounds__(256, 2)
sim_mma_kernel() {
    extern __shared__ uint32_t smsu[];
    const int tid = threadIdx.x;
    const int wid = tid >> 5, lane = tid & 31;
    const int warpM = wid >> 2, warpN = wid & 3;
    const int tg = lane & 3, gp = lane >> 2;
    const int split = blockIdx.x, b = blockIdx.y;
    const float* q = g_y + (size_t)b * C_ * N_;
    const int k0g = split * (N_ / SIM_SPLITS);

    const int bc = tid >> 1, bk2 = (tid & 1) * 8;

    float4 acc[4][4];
    #pragma unroll
    for (int m = 0; m < 4; m++)
        #pragma unroll
        for (int n = 0; n < 4; n++) acc[m][n] = make_float4(0.f, 0.f, 0.f, 0.f);

    sim_build16(smsu, smsu + SQ_TILE, q, k0g, bc, bk2);
    __syncthreads();

    const int NCH = (N_ / SIM_SPLITS) / 32;   // 16
    for (int ch = 0; ch < NCH; ch++) {
        const uint32_t* qh = smsu + (ch & 1) * (2 * SQ_TILE);
        const uint32_t* ql = qh + SQ_TILE;

        #pragma unroll
        for (int j2 = 0; j2 < 2; j2++) {
            const int k2a = j2 * 8 + tg;
            uint32_t ah[4][4], al[4][4];
            #pragma unroll
            for (int m = 0; m < 4; m++) {
                const int row = warpM * 64 + m * 16 + gp;
                ah[m][0] = qh[row * SQ_STR + k2a];
                ah[m][1] = qh[(row + 8) * SQ_STR + k2a];
                ah[m][2] = qh[row * SQ_STR + k2a + 4];
                ah[m][3] = qh[(row + 8) * SQ_STR + k2a + 4];
                al[m][0] = ql[row * SQ_STR + k2a];
                al[m][1] = ql[(row + 8) * SQ_STR + k2a];
                al[m][2] = ql[row * SQ_STR + k2a + 4];
                al[m][3] = ql[(row + 8) * SQ_STR + k2a + 4];
            }
            uint32_t bh0[4], bh1[4];
            #pragma unroll
            for (int nt = 0; nt < 4; nt++) {
                const int rb = warpN * 32 + nt * 8 + gp;
                bh0[nt] = qh[rb * SQ_STR + k2a];
                bh1[nt] = qh[rb * SQ_STR + k2a + 4];
            }
            #pragma unroll
            for (int m = 0; m < 4; m++)
                #pragma unroll
                for (int nt = 0; nt < 4; nt++) {
                    mma16816(acc[m][nt], ah[m][0], ah[m][1], ah[m][2], ah[m][3], bh0[nt], bh1[nt]);
                    mma16816(acc[m][nt], al[m][0], al[m][1], al[m][2], al[m][3], bh0[nt], bh1[nt]);
                }
        }
        if (ch + 1 < NCH)
            sim_build16(smsu + ((ch + 1) & 1) * (2 * SQ_TILE),
                        smsu + ((ch + 1) & 1) * (2 * SQ_TILE) + SQ_TILE,
                        q, k0g + (ch + 1) * 32, bc, bk2);
        __syncthreads();
    }

    float* dst = g_simp + (((size_t)(b * SIM_SPLITS + split)) * C_ * C_);
    #pragma unroll
    for (int m = 0; m < 4; m++) {
        const int c0 = warpM * 64 + m * 16 + gp;
        #pragma unroll
        for (int nt = 0; nt < 4; nt++) {
            const int d = warpN * 32 + nt * 8 + tg * 2;
            *(float2*)(dst + (size_t)c0 * C_ + d)       = make_float2(acc[m][nt].x, acc[m][nt].y);
            *(float2*)(dst + (size_t)(c0 + 8) * C_ + d) = make_float2(acc[m][nt].z, acc[m][nt].w);
        }
    }
}

// ===== 6. softmax(max - sim) == exp(min - sim)/sum =========================
__global__ void softmax_kernel() {
    const int c = blockIdx.x, b = blockIdx.y;
    const int d = threadIdx.x;
    float s = 0.f;
    #pragma unroll 8
    for (int sp = 0; sp < SIM_SPLITS; sp++)
        s += g_simp[(((size_t)(b * SIM_SPLITS + sp)) * C_ + c) * C_ + d];

    __shared__ float red[128];
    red[d] = s;
    __syncthreads();
    for (int st = 64; st > 0; st >>= 1) {
        if (d < st) red[d] = fminf(red[d], red[d + st]);
        __syncthreads();
    }
    const float mn = red[0];
    __syncthreads();
    const float e = expf(mn - s);
    red[d] = e;
    __syncthreads();
    for (int st = 64; st > 0; st >>= 1) {
        if (d < st) red[d] += red[d + st];
        __syncthreads();
    }
    g_p[(b * C_ + c) * C_ + d] = e / red[0];
}

// ===== 7. feat = P @ Q via pure fp16 mma (1-term); out = gamma*feat + y ====
#define FQ_STR 136
#define FQ_TILE (16 * FQ_STR)

__global__ void __launch_bounds__(256, 2)
feat_mma_kernel(const float* __restrict__ gamma, float* __restrict__ out) {
    extern __shared__ uint32_t fmsu[];
    uint32_t* Ph = fmsu;            // [c 128][d2 16] stride 20
    uint32_t* Qh = fmsu + SQ_TILE;  // [d2 16][n 128] stride 136

    const int tid = threadIdx.x;
    const int wid = tid >> 5, lane = tid & 31;
    const int warpM = wid >> 2, warpN = wid & 3;
    const int tg = lane & 3, gp = lane >> 2;
    const int n0 = blockIdx.x * 128, b = blockIdx.y;

    const float* qsrc = g_y + (size_t)b * C_ * N_;
    const float* psrc = g_p + (size_t)b * C_ * C_;

    float4 acc[4][4];
    #pragma unroll
    for (int m = 0; m < 4; m++)
        #pragma unroll
        for (int n = 0; n < 4; n++) acc[m][n] = make_float4(0.f, 0.f, 0.f, 0.f);

    const int pc = tid >> 1, pk2 = (tid & 1) * 8;
    const int qd2 = tid >> 4, qns = (tid & 15) * 8;

    for (int ch = 0; ch < 4; ch++) {
        const int d0 = ch * 32;
        __syncthreads();
        // P tile (hi only), pack from f32 probs
        {
            const float* src = psrc + (size_t)pc * C_ + d0 + 2 * pk2;
            #pragma unroll
            for (int e = 0; e < 8; e++) {
                float2 v = *(const float2*)(src + 2 * e);
                Ph[pc * SQ_STR + pk2 + e] =
                    pack2(__float2half_rn(v.x), __float2half_rn(v.y));
            }
        }
        // Q tile (hi only): pairs over d — two rows interleaved
        {
            const int r0 = d0 + 2 * qd2;
            const float* s0 = qsrc + (size_t)r0 * N_ + n0 + qns;
            const float* s1 = s0 + N_;
            float4 v0a = *(const float4*)s0;
            float4 v0b = *(const float4*)(s0 + 4);
            float4 v1a = *(const float4*)s1;
            float4 v1b = *(const float4*)(s1 + 4);
            const float v0[8] = {v0a.x, v0a.y, v0a.z, v0a.w, v0b.x, v0b.y, v0b.z, v0b.w};
            const float v1[8] = {v1a.x, v1a.y, v1a.z, v1a.w, v1b.x, v1b.y, v1b.z, v1b.w};
            #pragma unroll
            for (int e = 0; e < 8; e++)
                Qh[qd2 * FQ_STR + qns + e] =
                    pack2(__float2half_rn(v0[e]), __float2half_rn(v1[e]));
        }
        __syncthreads();

        #pragma unroll
        for (int j2 = 0; j2 < 2; j2++) {
            const int k2a = j2 * 8 + tg;
            uint32_t ah[4][4];
            #pragma unroll
            for (int m = 0; m < 4; m++) {
                const int row = warpM * 64 + m * 16 + gp;
                ah[m][0] = Ph[row * SQ_STR + k2a];
                ah[m][1] = Ph[(row + 8) * SQ_STR + k2a];
                ah[m][2] = Ph[row * SQ_STR + k2a + 4];
                ah[m][3] = Ph[(row + 8) * SQ_STR + k2a + 4];
            }
            uint32_t bh0[4], bh1[4];
            #pragma unroll
            for (int nt = 0; nt < 4; nt++) {
                const int cb = warpN * 32 + nt * 8 + gp;
                bh0[nt] = Qh[(k2a    ) * FQ_STR + cb];
                bh1[nt] = Qh[(k2a + 4) * FQ_STR + cb];
            }
            #pragma unroll
            for (int m = 0; m < 4; m++)
                #pragma unroll
                for (int nt = 0; nt < 4; nt++)
                    mma16816(acc[m][nt], ah[m][0], ah[m][1], ah[m][2], ah[m][3],
                             bh0[nt], bh1[nt]);
        }
    }

    const float g0 = gamma[0];
    #pragma unroll
    for (int m = 0; m < 4; m++) {
        const int co0 = warpM * 64 + m * 16 + gp;
        const int co1 = co0 + 8;
        #pragma unroll
        for (int nt = 0; nt < 4; nt++) {
            const int w = warpN * 32 + nt * 8 + tg * 2;
            const size_t a0 = ((size_t)(b * C_ + co0)) * N_ + n0 + w;
            const size_t a1 = ((size_t)(b * C_ + co1)) * N_ + n0 + w;
            float2 y0 = *(const float2*)(g_y + a0);
            float2 y1 = *(const float2*)(g_y + a1);
            float2 o0, o1;
            o0.x = g0 * acc[m][nt].x + y0.x;  o0.y = g0 * acc[m][nt].y + y0.y;
            o1.x = g0 * acc[m][nt].z + y1.x;  o1.y = g0 * acc[m][nt].w + y1.y;
            *(float2*)(out + a0) = o0;
            *(float2*)(out + a1) = o1;
        }
    }
}

// ===== launch ==============================================================
extern "C" void kernel_launch(void* const* d_in, const int* in_sizes, int n_in,
                              void* d_out, int out_size) {
    const float* x1       = (const float*)d_in[0];
    const float* x2       = (const float*)d_in[1];
    const float* se_w1    = (const float*)d_in[2];
    const float* se_w2    = (const float*)d_in[3];
    const float* conv_w   = (const float*)d_in[4];
    const float* bn_gamma = (const float*)d_in[5];
    const float* bn_beta  = (const float*)d_in[6];
    const float* bn_mean  = (const float*)d_in[7];
    const float* bn_var   = (const float*)d_in[8];
    const float* gamma    = (const float*)d_in[9];
    float* out = (float*)d_out;

    const int cv_smem   = 4 * CB_TILE * 4 + 2 * RAW_BUF * 4;  // 75776
    const int sim_smem  = 4 * SQ_TILE * 4;                    // 40960
    const int feat_smem = (SQ_TILE + FQ_TILE) * 4;            // 18944
    cudaFuncSetAttribute(conv_mma_kernel, cudaFuncAttributeMaxDynamicSharedMemorySize, cv_smem);

    prep_wf16_kernel<<<(144 * 8 * 2 * 32 + 255) / 256, 256>>>(conv_w);
    avgpool_kernel<<<B_ * C2_, 256>>>(x1, x2);
    se_mlp_kernel<<<1, C2_>>>(se_w1, se_w2);
    conv_mma_kernel<<<dim3(HW_, B_), 256, cv_smem>>>(x1, x2, bn_gamma, bn_beta, bn_mean, bn_var);
    sim_mma_kernel<<<dim3(SIM_SPLITS, B_), 256, sim_smem>>>();
    softmax_kernel<<<dim3(C_, B_), 128>>>();
    feat_mma_kernel<<<dim3(N_ / 128, B_), 256, feat_smem>>>(gamma, out);
}